// round 2
// baseline (speedup 1.0000x reference)
#include <cuda_runtime.h>
#include <cstdint>
#include <cstddef>

#define BB    16
#define T_EN  1024
#define C_IN  512
#define C_H   256
#define KSZ   5
#define T_DE_MAX 3072

typedef unsigned long long ull;

// ---------------- device scratch (no runtime allocation allowed) ----------------
__device__ float g_h1[(size_t)BB * T_EN * C_H];        // conv1 output (post-LN)
__device__ float g_w1t[C_H * C_IN * KSZ];              // conv1 weights, [co][ci2][k][parity]
__device__ float g_w2t[C_H * C_H * KSZ];               // conv2 weights, same layout
__device__ int   g_txmap[BB * T_DE_MAX];               // ty -> tx map (-1 = outside mel_len)
__device__ int   g_srclen[BB];

// ---------------- packed f32x2 helpers ----------------
__device__ __forceinline__ void fma2(ull& d, ull a, ull b) {
    asm("fma.rn.f32x2 %0, %1, %2, %0;" : "+l"(d) : "l"(a), "l"(b));
}
__device__ __forceinline__ float2 upk(ull v) {
    float2 f; asm("mov.b64 {%0, %1}, %2;" : "=f"(f.x), "=f"(f.y) : "l"(v)); return f;
}

// ---------------- weight re-layout: [co][ci][k] -> [co][ci/2][k][ci&1] ----------------
__global__ void wt_kernel(const float* __restrict__ w1, const float* __restrict__ w2) {
    const int n1 = C_H * C_IN * KSZ;
    for (int i = blockIdx.x * blockDim.x + threadIdx.x; i < n1; i += gridDim.x * blockDim.x) {
        int k  = i % KSZ;
        int ci = (i / KSZ) % C_IN;
        int co = i / (KSZ * C_IN);
        g_w1t[((co * (C_IN / 2) + (ci >> 1)) * KSZ + k) * 2 + (ci & 1)] = w1[i];
    }
    const int n2 = C_H * C_H * KSZ;
    for (int i = blockIdx.x * blockDim.x + threadIdx.x; i < n2; i += gridDim.x * blockDim.x) {
        int k  = i % KSZ;
        int ci = (i / KSZ) % C_H;
        int co = i / (KSZ * C_H);
        g_w2t[((co * (C_H / 2) + (ci >> 1)) * KSZ + k) * 2 + (ci & 1)] = w2[i];
    }
}

// ---------------- duration cumsum + ty->tx map + src_len ----------------
__global__ void scan_kernel(const float* __restrict__ dur, int tde) {
    __shared__ float s[T_EN];
    __shared__ int cnt;
    int b = blockIdx.x, t = threadIdx.x;
    if (t == 0) cnt = 0;
    float d = dur[b * T_EN + t];
    s[t] = d;
    __syncthreads();
    if (d > 0.f) atomicAdd(&cnt, 1);
    for (int off = 1; off < T_EN; off <<= 1) {
        float v = s[t];
        if (t >= off) v += s[t - off];
        __syncthreads();
        s[t] = v;
        __syncthreads();
    }
    for (int y = t; y < tde; y += T_EN) g_txmap[b * T_DE_MAX + y] = -1;
    __syncthreads();
    if (d > 0.f) {
        int e  = (int)(s[t] + 0.5f);
        int st = (t > 0) ? (int)(s[t - 1] + 0.5f) : 0;
        for (int y = st; y < e && y < tde; y++) g_txmap[b * T_DE_MAX + y] = t;
    }
    if (t == 0) g_srclen[b] = cnt;
}

// ---------------- conv1 (512->256, K=5) + relu + LN -> g_h1 ----------------
__global__ __launch_bounds__(256, 2) void conv1_kernel(
    const float* __restrict__ xin, const float* __restrict__ bias,
    const float* __restrict__ lng, const float* __restrict__ lnb)
{
    __shared__ float xs[20 * C_IN];
    __shared__ float ms[16], vs[16];
    int b = blockIdx.y;
    int t0 = blockIdx.x * 16;
    int sl = g_srclen[b];
    if (t0 > sl + 1) return;   // h1 only needed for t <= src_len+1
    int tid = threadIdx.x;

    const float4* src = (const float4*)(xin + (size_t)b * T_EN * C_IN);
    float4* xs4 = (float4*)xs;
    for (int i = tid; i < 20 * (C_IN / 4); i += 256) {
        int r = i / (C_IN / 4), c4 = i % (C_IN / 4);
        int gr = t0 - 2 + r;
        float4 v = make_float4(0.f, 0.f, 0.f, 0.f);
        if (gr >= 0 && gr < T_EN) v = src[(size_t)gr * (C_IN / 4) + c4];
        xs4[i] = v;
    }
    __syncthreads();

    int co = tid;
    ull acc[16];
#pragma unroll
    for (int t = 0; t < 16; t++) acc[t] = 0ull;
    const ull* wrow = (const ull*)(g_w1t + (size_t)co * C_IN * KSZ);
#pragma unroll 2
    for (int ci2 = 0; ci2 < C_IN / 2; ci2++) {
        ull xv[20];
#pragma unroll
        for (int r = 0; r < 20; r++) xv[r] = *(const ull*)(xs + r * C_IN + 2 * ci2);
#pragma unroll
        for (int k = 0; k < KSZ; k++) {
            ull w = wrow[ci2 * KSZ + k];
#pragma unroll
            for (int t = 0; t < 16; t++) fma2(acc[t], w, xv[t + k]);
        }
    }
    __syncthreads();   // done reading xs; reuse as reduction buffer

    float* sv = xs;
    float bco = bias[co];
    float vals[16];
#pragma unroll
    for (int t = 0; t < 16; t++) {
        float2 p = upk(acc[t]);
        float v = fmaxf(p.x + p.y + bco, 0.f);
        vals[t] = v;
        sv[t * C_H + co] = v;
    }
    __syncthreads();

    int wid = tid >> 5, lane = tid & 31;
#pragma unroll
    for (int tt = wid * 2; tt < wid * 2 + 2; tt++) {
        float s = 0.f, s2 = 0.f;
#pragma unroll
        for (int j = 0; j < C_H; j += 32) { float v = sv[tt * C_H + j + lane]; s += v; s2 += v * v; }
#pragma unroll
        for (int o = 16; o; o >>= 1) {
            s  += __shfl_xor_sync(0xffffffffu, s, o);
            s2 += __shfl_xor_sync(0xffffffffu, s2, o);
        }
        if (lane == 0) { float m = s * (1.f / C_H); ms[tt] = m; vs[tt] = s2 * (1.f / C_H) - m * m; }
    }
    __syncthreads();

    float g = lng[co], bb = lnb[co];
    float* h1 = g_h1 + ((size_t)b * T_EN + t0) * C_H + co;
#pragma unroll
    for (int t = 0; t < 16; t++) {
        float r = rsqrtf(vs[t] + 1e-5f);
        h1[(size_t)t * C_H] = (vals[t] - ms[t]) * r * g + bb;
    }
}

// ---------------- conv2 (256->256, K=5) + relu + LN + linear -> log_duration_pred ----------------
__global__ __launch_bounds__(256, 2) void conv2_kernel(
    const float* __restrict__ bias, const float* __restrict__ lng, const float* __restrict__ lnb,
    const float* __restrict__ lw, const float* __restrict__ lb, float* __restrict__ out2)
{
    __shared__ float xs[20 * C_H];
    __shared__ float ms[16], vs[16];
    int b = blockIdx.y;
    int t0 = blockIdx.x * 16;
    int sl = g_srclen[b];
    int tid = threadIdx.x;
    if (t0 >= sl) {                       // fully masked tile -> zeros
        if (tid < 16) out2[b * T_EN + t0 + tid] = 0.f;
        return;
    }
    const float4* src = (const float4*)(g_h1 + (size_t)b * T_EN * C_H);
    float4* xs4 = (float4*)xs;
    for (int i = tid; i < 20 * (C_H / 4); i += 256) {
        int r = i / (C_H / 4), c4 = i % (C_H / 4);
        int gr = t0 - 2 + r;
        float4 v = make_float4(0.f, 0.f, 0.f, 0.f);
        if (gr >= 0 && gr < T_EN) v = src[(size_t)gr * (C_H / 4) + c4];
        xs4[i] = v;
    }
    __syncthreads();

    int co = tid;
    ull acc[16];
#pragma unroll
    for (int t = 0; t < 16; t++) acc[t] = 0ull;
    const ull* wrow = (const ull*)(g_w2t + (size_t)co * C_H * KSZ);
#pragma unroll 2
    for (int ci2 = 0; ci2 < C_H / 2; ci2++) {
        ull xv[20];
#pragma unroll
        for (int r = 0; r < 20; r++) xv[r] = *(const ull*)(xs + r * C_H + 2 * ci2);
#pragma unroll
        for (int k = 0; k < KSZ; k++) {
            ull w = wrow[ci2 * KSZ + k];
#pragma unroll
            for (int t = 0; t < 16; t++) fma2(acc[t], w, xv[t + k]);
        }
    }
    __syncthreads();

    float* sv = xs;
    float bco = bias[co];
    float vals[16];
#pragma unroll
    for (int t = 0; t < 16; t++) {
        float2 p = upk(acc[t]);
        float v = fmaxf(p.x + p.y + bco, 0.f);
        vals[t] = v;
        sv[t * C_H + co] = v;
    }
    __syncthreads();

    int wid = tid >> 5, lane = tid & 31;
#pragma unroll
    for (int tt = wid * 2; tt < wid * 2 + 2; tt++) {
        float s = 0.f, s2 = 0.f;
#pragma unroll
        for (int j = 0; j < C_H; j += 32) { float v = sv[tt * C_H + j + lane]; s += v; s2 += v * v; }
#pragma unroll
        for (int o = 16; o; o >>= 1) {
            s  += __shfl_xor_sync(0xffffffffu, s, o);
            s2 += __shfl_xor_sync(0xffffffffu, s2, o);
        }
        if (lane == 0) { float m = s * (1.f / C_H); ms[tt] = m; vs[tt] = s2 * (1.f / C_H) - m * m; }
    }
    __syncthreads();

    // normalize, multiply by linear weight, block-reduce per t
    float g = lng[co], bb = lnb[co], lwc = lw[co];
#pragma unroll
    for (int t = 0; t < 16; t++) {
        float r = rsqrtf(vs[t] + 1e-5f);
        float n = (vals[t] - ms[t]) * r * g + bb;
        sv[t * C_H + co] = n * lwc;
    }
    __syncthreads();
    float lbv = lb[0];
#pragma unroll
    for (int tt = wid * 2; tt < wid * 2 + 2; tt++) {
        float s = 0.f;
#pragma unroll
        for (int j = 0; j < C_H; j += 32) s += sv[tt * C_H + j + lane];
#pragma unroll
        for (int o = 16; o; o >>= 1) s += __shfl_xor_sync(0xffffffffu, s, o);
        if (lane == 0) {
            int t = t0 + tt;
            out2[b * T_EN + t] = (t < sl) ? (s + lbv) : 0.f;
        }
    }
}

// ---------------- scatter ones into attn^T ----------------
__global__ void ones_kernel(float* __restrict__ out4, int tde) {
    int i = blockIdx.x * blockDim.x + threadIdx.x;
    if (i >= BB * tde) return;
    int b = i / tde, ty = i % tde;
    int tx = g_txmap[b * T_DE_MAX + ty];
    if (tx >= 0) out4[((size_t)b * tde + ty) * T_EN + tx] = 1.0f;
}

// ---------------- encoder_output gather: out3[b][c][ty] = enc[b][tx(ty)][c] ----------------
__global__ void gather3_kernel(const float* __restrict__ enc, float* __restrict__ out3, int tde) {
    int b = blockIdx.y;
    int ty = blockIdx.x * 256 + threadIdx.x;
    if (ty >= tde) return;
    int tx = g_txmap[b * T_DE_MAX + ty];
    float* ob = out3 + (size_t)b * C_IN * tde + ty;
    if (tx < 0) {
        for (int c = 0; c < C_IN; c++) ob[(size_t)c * tde] = 0.f;
    } else {
        const float4* e4 = (const float4*)(enc + ((size_t)b * T_EN + tx) * C_IN);
        for (int c4 = 0; c4 < C_IN / 4; c4++) {
            float4 v = e4[c4];
            ob[(size_t)(4 * c4 + 0) * tde] = v.x;
            ob[(size_t)(4 * c4 + 1) * tde] = v.y;
            ob[(size_t)(4 * c4 + 2) * tde] = v.z;
            ob[(size_t)(4 * c4 + 3) * tde] = v.w;
        }
    }
}

// ---------------- launcher ----------------
extern "C" void kernel_launch(void* const* d_in, const int* in_sizes, int n_in,
                              void* d_out, int out_size) {
    const float* enc    = (const float*)d_in[0];   // encoder_output
    const float* encres = (const float*)d_in[1];   // encoder_output_res
    const float* dur    = (const float*)d_in[2];   // duration_target
    const float* c1w    = (const float*)d_in[3];
    const float* c1b    = (const float*)d_in[4];
    const float* g1     = (const float*)d_in[5];
    const float* b1     = (const float*)d_in[6];
    const float* c2w    = (const float*)d_in[7];
    const float* c2b    = (const float*)d_in[8];
    const float* g2     = (const float*)d_in[9];
    const float* b2     = (const float*)d_in[10];
    const float* lw     = (const float*)d_in[11];
    const float* lb     = (const float*)d_in[12];
    // d_in[13] src_mask (derived from duration instead), d_in[14] mel_lens (derived from cumsum)

    float* out = (float*)d_out;
    // out_size = T_DE*(B*T_EN + B*C_IN + B*T_EN) + B*T_EN
    int tde = (int)(((long long)out_size - (long long)BB * T_EN) /
                    (2LL * BB * T_EN + (long long)BB * C_IN));
    if (tde <= 0 || tde > T_DE_MAX) return;

    float* out1 = out;                                    // [B, T_EN, T_DE] (all zeros)
    float* out2 = out1 + (size_t)BB * T_EN * tde;         // [B, T_EN] log_duration_pred
    float* out3 = out2 + (size_t)BB * T_EN;               // [B, C_IN, T_DE] einsum result
    float* out4 = out3 + (size_t)BB * C_IN * tde;         // [B, T_DE, T_EN] attn^T

    // out1 is exactly zero (masked predictor -> zero durations -> empty path).
    // out4 is zeros + one-hot scatter. out2/out3 fully overwritten below.
    cudaMemsetAsync(out1, 0, (size_t)BB * T_EN * tde * sizeof(float));
    cudaMemsetAsync(out4, 0, (size_t)BB * T_EN * tde * sizeof(float));

    wt_kernel<<<512, 256>>>(c1w, c2w);
    scan_kernel<<<BB, T_EN>>>(dur, tde);
    conv1_kernel<<<dim3(T_EN / 16, BB), 256>>>(encres, c1b, g1, b1);
    conv2_kernel<<<dim3(T_EN / 16, BB), 256>>>(c2b, g2, b2, lw, lb, out2);
    ones_kernel<<<(BB * tde + 255) / 256, 256>>>(out4, tde);
    gather3_kernel<<<dim3((tde + 255) / 256, BB), 256>>>(enc, out3, tde);
}

// round 3
// speedup vs baseline: 2.7237x; 2.7237x over previous
#include <cuda_runtime.h>
#include <cstdint>
#include <cstddef>

#define BB    16
#define T_EN  1024
#define C_IN  512
#define C_H   256
#define KSZ   5
#define T_DE_MAX 3072

typedef unsigned long long ull;

// ---------------- device scratch (no runtime allocation allowed) ----------------
__device__ float g_h1[(size_t)BB * T_EN * C_H];        // conv1 output (post-LN)
// weights re-laid out as [ci2][k][co][parity] -> warp-coalesced ull loads
__device__ float g_w1t[C_H * C_IN * KSZ];
__device__ float g_w2t[C_H * C_H * KSZ];
__device__ int   g_txmap[BB * T_DE_MAX];               // ty -> tx map (-1 = outside mel_len)
__device__ int   g_srclen[BB];

// ---------------- packed f32x2 helpers ----------------
__device__ __forceinline__ void fma2(ull& d, ull a, ull b) {
    asm("fma.rn.f32x2 %0, %1, %2, %0;" : "+l"(d) : "l"(a), "l"(b));
}
__device__ __forceinline__ float2 upk(ull v) {
    float2 f; asm("mov.b64 {%0, %1}, %2;" : "=f"(f.x), "=f"(f.y) : "l"(v)); return f;
}

// ---------------- weight re-layout: [co][ci][k] -> [ci2][k][co][ci&1] ----------------
__global__ void wt_kernel(const float* __restrict__ w1, const float* __restrict__ w2) {
    const int n1 = C_H * C_IN * KSZ;
    for (int i = blockIdx.x * blockDim.x + threadIdx.x; i < n1; i += gridDim.x * blockDim.x) {
        int k  = i % KSZ;
        int ci = (i / KSZ) % C_IN;
        int co = i / (KSZ * C_IN);
        g_w1t[((((ci >> 1) * KSZ) + k) * C_H + co) * 2 + (ci & 1)] = w1[i];
    }
    const int n2 = C_H * C_H * KSZ;
    for (int i = blockIdx.x * blockDim.x + threadIdx.x; i < n2; i += gridDim.x * blockDim.x) {
        int k  = i % KSZ;
        int ci = (i / KSZ) % C_H;
        int co = i / (KSZ * C_H);
        g_w2t[((((ci >> 1) * KSZ) + k) * C_H + co) * 2 + (ci & 1)] = w2[i];
    }
}

// ---------------- duration cumsum + ty->tx map + src_len ----------------
__global__ void scan_kernel(const float* __restrict__ dur, int tde) {
    __shared__ float s[T_EN];
    __shared__ int cnt;
    int b = blockIdx.x, t = threadIdx.x;
    if (t == 0) cnt = 0;
    float d = dur[b * T_EN + t];
    s[t] = d;
    __syncthreads();
    if (d > 0.f) atomicAdd(&cnt, 1);
    for (int off = 1; off < T_EN; off <<= 1) {
        float v = s[t];
        if (t >= off) v += s[t - off];
        __syncthreads();
        s[t] = v;
        __syncthreads();
    }
    for (int y = t; y < tde; y += T_EN) g_txmap[b * T_DE_MAX + y] = -1;
    __syncthreads();
    if (d > 0.f) {
        int e  = (int)(s[t] + 0.5f);
        int st = (t > 0) ? (int)(s[t - 1] + 0.5f) : 0;
        for (int y = st; y < e && y < tde; y++) g_txmap[b * T_DE_MAX + y] = t;
    }
    if (t == 0) g_srclen[b] = cnt;
}

// ============== conv core: one live x value, acc[16] chains, coalesced weights ==============
template<int CCH>
__device__ __forceinline__ void conv_body(const float* __restrict__ xs,
                                          const float* __restrict__ wsrc,
                                          int co, ull (&acc)[16]) {
#pragma unroll
    for (int t = 0; t < 16; t++) acc[t] = 0ull;
#pragma unroll 2
    for (int ci2 = 0; ci2 < CCH / 2; ci2++) {
        ull w[KSZ];
#pragma unroll
        for (int k = 0; k < KSZ; k++)
            w[k] = *(const ull*)(wsrc + (((size_t)ci2 * KSZ + k) * C_H + co) * 2);
        const float* xp = xs + 2 * ci2;
#pragma unroll
        for (int r = 0; r < 20; r++) {
            ull x = *(const ull*)(xp + r * CCH);
#pragma unroll
            for (int k = 0; k < KSZ; k++) {
                int t = r - k;
                if (t >= 0 && t < 16) fma2(acc[t], w[k], x);
            }
        }
    }
}

// ---------------- conv1 (512->256, K=5) + relu + LN -> g_h1 ----------------
__global__ __launch_bounds__(256, 3) void conv1_kernel(
    const float* __restrict__ xin, const float* __restrict__ bias,
    const float* __restrict__ lng, const float* __restrict__ lnb)
{
    __shared__ __align__(16) float xs[20 * C_IN];
    __shared__ float ms[16], vs[16];
    int b = blockIdx.y;
    int t0 = blockIdx.x * 16;
    int sl = g_srclen[b];
    if (t0 > sl + 1) return;   // h1 only needed for t <= src_len+1 (+slack)
    int tid = threadIdx.x;

    const float4* src = (const float4*)(xin + (size_t)b * T_EN * C_IN);
    float4* xs4 = (float4*)xs;
    for (int i = tid; i < 20 * (C_IN / 4); i += 256) {
        int r = i / (C_IN / 4), c4 = i % (C_IN / 4);
        int gr = t0 - 2 + r;
        float4 v = make_float4(0.f, 0.f, 0.f, 0.f);
        if (gr >= 0 && gr < T_EN) v = src[(size_t)gr * (C_IN / 4) + c4];
        xs4[i] = v;
    }
    __syncthreads();

    int co = tid;
    ull acc[16];
    conv_body<C_IN>(xs, g_w1t, co, acc);
    __syncthreads();   // done reading xs; reuse as reduction buffer

    float* sv = xs;
    float bco = bias[co];
    float vals[16];
#pragma unroll
    for (int t = 0; t < 16; t++) {
        float2 p = upk(acc[t]);
        float v = fmaxf(p.x + p.y + bco, 0.f);
        vals[t] = v;
        sv[t * C_H + co] = v;
    }
    __syncthreads();

    int wid = tid >> 5, lane = tid & 31;
#pragma unroll
    for (int tt = wid * 2; tt < wid * 2 + 2; tt++) {
        float s = 0.f, s2 = 0.f;
#pragma unroll
        for (int j = 0; j < C_H; j += 32) { float v = sv[tt * C_H + j + lane]; s += v; s2 += v * v; }
#pragma unroll
        for (int o = 16; o; o >>= 1) {
            s  += __shfl_xor_sync(0xffffffffu, s, o);
            s2 += __shfl_xor_sync(0xffffffffu, s2, o);
        }
        if (lane == 0) { float m = s * (1.f / C_H); ms[tt] = m; vs[tt] = s2 * (1.f / C_H) - m * m; }
    }
    __syncthreads();

    float g = lng[co], bb = lnb[co];
    float* h1 = g_h1 + ((size_t)b * T_EN + t0) * C_H + co;
#pragma unroll
    for (int t = 0; t < 16; t++) {
        float r = rsqrtf(vs[t] + 1e-5f);
        h1[(size_t)t * C_H] = (vals[t] - ms[t]) * r * g + bb;
    }
}

// ---------------- conv2 (256->256, K=5) + relu + LN + linear -> log_duration_pred ----------------
__global__ __launch_bounds__(256, 3) void conv2_kernel(
    const float* __restrict__ bias, const float* __restrict__ lng, const float* __restrict__ lnb,
    const float* __restrict__ lw, const float* __restrict__ lb, float* __restrict__ out2)
{
    __shared__ __align__(16) float xs[20 * C_H];
    __shared__ float ms[16], vs[16];
    int b = blockIdx.y;
    int t0 = blockIdx.x * 16;
    int sl = g_srclen[b];
    int tid = threadIdx.x;
    if (t0 >= sl) {                       // fully masked tile -> zeros
        if (tid < 16) out2[b * T_EN + t0 + tid] = 0.f;
        return;
    }
    const float4* src = (const float4*)(g_h1 + (size_t)b * T_EN * C_H);
    float4* xs4 = (float4*)xs;
    for (int i = tid; i < 20 * (C_H / 4); i += 256) {
        int r = i / (C_H / 4), c4 = i % (C_H / 4);
        int gr = t0 - 2 + r;
        float4 v = make_float4(0.f, 0.f, 0.f, 0.f);
        if (gr >= 0 && gr < T_EN) v = src[(size_t)gr * (C_H / 4) + c4];
        xs4[i] = v;
    }
    __syncthreads();

    int co = tid;
    ull acc[16];
    conv_body<C_H>(xs, g_w2t, co, acc);
    __syncthreads();

    float* sv = xs;
    float bco = bias[co];
    float vals[16];
#pragma unroll
    for (int t = 0; t < 16; t++) {
        float2 p = upk(acc[t]);
        float v = fmaxf(p.x + p.y + bco, 0.f);
        vals[t] = v;
        sv[t * C_H + co] = v;
    }
    __syncthreads();

    int wid = tid >> 5, lane = tid & 31;
#pragma unroll
    for (int tt = wid * 2; tt < wid * 2 + 2; tt++) {
        float s = 0.f, s2 = 0.f;
#pragma unroll
        for (int j = 0; j < C_H; j += 32) { float v = sv[tt * C_H + j + lane]; s += v; s2 += v * v; }
#pragma unroll
        for (int o = 16; o; o >>= 1) {
            s  += __shfl_xor_sync(0xffffffffu, s, o);
            s2 += __shfl_xor_sync(0xffffffffu, s2, o);
        }
        if (lane == 0) { float m = s * (1.f / C_H); ms[tt] = m; vs[tt] = s2 * (1.f / C_H) - m * m; }
    }
    __syncthreads();

    // normalize, multiply by linear weight, block-reduce per t
    float g = lng[co], bb = lnb[co], lwc = lw[co];
#pragma unroll
    for (int t = 0; t < 16; t++) {
        float r = rsqrtf(vs[t] + 1e-5f);
        float n = (vals[t] - ms[t]) * r * g + bb;
        sv[t * C_H + co] = n * lwc;
    }
    __syncthreads();
    float lbv = lb[0];
#pragma unroll
    for (int tt = wid * 2; tt < wid * 2 + 2; tt++) {
        float s = 0.f;
#pragma unroll
        for (int j = 0; j < C_H; j += 32) s += sv[tt * C_H + j + lane];
#pragma unroll
        for (int o = 16; o; o >>= 1) s += __shfl_xor_sync(0xffffffffu, s, o);
        if (lane == 0) {
            int t = t0 + tt;
            out2[b * T_EN + t] = (t < sl) ? (s + lbv) : 0.f;
        }
    }
}

// ---------------- scatter ones into attn^T ----------------
__global__ void ones_kernel(float* __restrict__ out4, int tde) {
    int i = blockIdx.x * blockDim.x + threadIdx.x;
    if (i >= BB * tde) return;
    int b = i / tde, ty = i % tde;
    int tx = g_txmap[b * T_DE_MAX + ty];
    if (tx >= 0) out4[((size_t)b * tde + ty) * T_EN + tx] = 1.0f;
}

// ---------------- encoder_output gather: out3[b][c][ty] = enc[b][tx(ty)][c] ----------------
__global__ void gather3_kernel(const float* __restrict__ enc, float* __restrict__ out3, int tde) {
    int b = blockIdx.y;
    int ty = blockIdx.x * 256 + threadIdx.x;
    if (ty >= tde) return;
    int tx = g_txmap[b * T_DE_MAX + ty];
    float* ob = out3 + (size_t)b * C_IN * tde + ty;
    if (tx < 0) {
        for (int c = 0; c < C_IN; c++) ob[(size_t)c * tde] = 0.f;
    } else {
        const float4* e4 = (const float4*)(enc + ((size_t)b * T_EN + tx) * C_IN);
        for (int c4 = 0; c4 < C_IN / 4; c4++) {
            float4 v = e4[c4];
            ob[(size_t)(4 * c4 + 0) * tde] = v.x;
            ob[(size_t)(4 * c4 + 1) * tde] = v.y;
            ob[(size_t)(4 * c4 + 2) * tde] = v.z;
            ob[(size_t)(4 * c4 + 3) * tde] = v.w;
        }
    }
}

// ---------------- launcher ----------------
extern "C" void kernel_launch(void* const* d_in, const int* in_sizes, int n_in,
                              void* d_out, int out_size) {
    const float* enc    = (const float*)d_in[0];   // encoder_output
    const float* encres = (const float*)d_in[1];   // encoder_output_res
    const float* dur    = (const float*)d_in[2];   // duration_target
    const float* c1w    = (const float*)d_in[3];
    const float* c1b    = (const float*)d_in[4];
    const float* g1     = (const float*)d_in[5];
    const float* b1     = (const float*)d_in[6];
    const float* c2w    = (const float*)d_in[7];
    const float* c2b    = (const float*)d_in[8];
    const float* g2     = (const float*)d_in[9];
    const float* b2     = (const float*)d_in[10];
    const float* lw     = (const float*)d_in[11];
    const float* lb     = (const float*)d_in[12];

    float* out = (float*)d_out;
    int tde = (int)(((long long)out_size - (long long)BB * T_EN) /
                    (2LL * BB * T_EN + (long long)BB * C_IN));
    if (tde <= 0 || tde > T_DE_MAX) return;

    float* out1 = out;                                    // [B, T_EN, T_DE] (all zeros)
    float* out2 = out1 + (size_t)BB * T_EN * tde;         // [B, T_EN] log_duration_pred
    float* out3 = out2 + (size_t)BB * T_EN;               // [B, C_IN, T_DE] einsum result
    float* out4 = out3 + (size_t)BB * C_IN * tde;         // [B, T_DE, T_EN] attn^T

    cudaMemsetAsync(out1, 0, (size_t)BB * T_EN * tde * sizeof(float));
    cudaMemsetAsync(out4, 0, (size_t)BB * T_EN * tde * sizeof(float));

    wt_kernel<<<512, 256>>>(c1w, c2w);
    scan_kernel<<<BB, T_EN>>>(dur, tde);
    conv1_kernel<<<dim3(T_EN / 16, BB), 256>>>(encres, c1b, g1, b1);
    conv2_kernel<<<dim3(T_EN / 16, BB), 256>>>(c2b, g2, b2, lw, lb, out2);
    ones_kernel<<<(BB * tde + 255) / 256, 256>>>(out4, tde);
    gather3_kernel<<<dim3((tde + 255) / 256, BB), 256>>>(enc, out3, tde);
}

// round 11
// speedup vs baseline: 4.9530x; 1.8185x over previous
#include <cuda_runtime.h>
#include <cuda_bf16.h>
#include <cstdint>
#include <cstddef>

#define BB    16
#define T_EN  1024
#define C_IN  512
#define C_H   256
#define KSZ   5
#define T_DE_MAX 3072

typedef unsigned long long ull;

// ---------------- device scratch (no runtime allocation allowed) ----------------
// split-bf16 representation: value = hi + lo, hi = bf16(v), lo = bf16(v - hi)
__device__ __nv_bfloat16 g_xh [(size_t)BB * T_EN * C_IN];
__device__ __nv_bfloat16 g_xl [(size_t)BB * T_EN * C_IN];
__device__ __nv_bfloat16 g_h1h[(size_t)BB * T_EN * C_H];
__device__ __nv_bfloat16 g_h1l[(size_t)BB * T_EN * C_H];
// pre-swizzled B-operand stage blocks: stage = k*(CCH/64)+ci/64, block = [co 0..255][64 k-cols] SW128
__device__ __nv_bfloat16 g_w1h[40 * 16384];
__device__ __nv_bfloat16 g_w1l[40 * 16384];
__device__ __nv_bfloat16 g_w2h[20 * 16384];
__device__ __nv_bfloat16 g_w2l[20 * 16384];
__device__ int g_txmap[BB * T_DE_MAX];
__device__ int g_srclen[BB];

// ---------------- PTX helpers (portable: sm_80+) ----------------
__device__ __forceinline__ uint32_t smem_u32(const void* p) {
    uint32_t a;
    asm("{ .reg .u64 t; cvta.to.shared.u64 t, %1; cvt.u32.u64 %0, t; }" : "=r"(a) : "l"(p));
    return a;
}
#define SW128(o) ((o) ^ (((o) >> 3) & 0x70))

__device__ __forceinline__ void cp16(uint32_t dst, const void* src) {
    asm volatile("cp.async.cg.shared.global [%0], [%1], 16;" :: "r"(dst), "l"(src) : "memory");
}
__device__ __forceinline__ void cpcommit() { asm volatile("cp.async.commit_group;" ::: "memory"); }
template<int N>
__device__ __forceinline__ void cpwait() { asm volatile("cp.async.wait_group %0;" :: "n"(N) : "memory"); }

__device__ __forceinline__ void ldsm4(uint32_t* f, uint32_t addr) {
    asm volatile("ldmatrix.sync.aligned.m8n8.x4.shared.b16 {%0, %1, %2, %3}, [%4];"
                 : "=r"(f[0]), "=r"(f[1]), "=r"(f[2]), "=r"(f[3]) : "r"(addr));
}
__device__ __forceinline__ void mma16816(float* c, const uint32_t* a, uint32_t b0, uint32_t b1) {
    asm("mma.sync.aligned.m16n8k16.row.col.f32.bf16.bf16.f32 "
        "{%0, %1, %2, %3}, {%4, %5, %6, %7}, {%8, %9}, {%0, %1, %2, %3};"
        : "+f"(c[0]), "+f"(c[1]), "+f"(c[2]), "+f"(c[3])
        : "r"(a[0]), "r"(a[1]), "r"(a[2]), "r"(a[3]), "r"(b0), "r"(b1));
}

__device__ __forceinline__ void split_bf16(float v, __nv_bfloat16& h, __nv_bfloat16& l) {
    h = __float2bfloat16(v);
    l = __float2bfloat16(v - __bfloat162float(h));
}

// ---------------- weight prep: fp32 [co][ci][k] -> split-bf16 pre-swizzled stage blocks ----------------
__global__ void wtb_kernel(const float* __restrict__ w1, const float* __restrict__ w2) {
    const int n1 = C_H * C_IN * KSZ;
    for (int i = blockIdx.x * blockDim.x + threadIdx.x; i < n1; i += gridDim.x * blockDim.x) {
        int k  = i % KSZ;
        int ci = (i / KSZ) % C_IN;
        int co = i / (KSZ * C_IN);
        int stage = k * (C_IN / 64) + (ci >> 6);
        int col = ci & 63;
        size_t off = (size_t)stage * 32768 + SW128((uint32_t)(co * 128 + col * 2));
        __nv_bfloat16 h, l; split_bf16(w1[i], h, l);
        *(__nv_bfloat16*)((char*)g_w1h + off) = h;
        *(__nv_bfloat16*)((char*)g_w1l + off) = l;
    }
    const int n2 = C_H * C_H * KSZ;
    for (int i = blockIdx.x * blockDim.x + threadIdx.x; i < n2; i += gridDim.x * blockDim.x) {
        int k  = i % KSZ;
        int ci = (i / KSZ) % C_H;
        int co = i / (KSZ * C_H);
        int stage = k * (C_H / 64) + (ci >> 6);
        int col = ci & 63;
        size_t off = (size_t)stage * 32768 + SW128((uint32_t)(co * 128 + col * 2));
        __nv_bfloat16 h, l; split_bf16(w2[i], h, l);
        *(__nv_bfloat16*)((char*)g_w2h + off) = h;
        *(__nv_bfloat16*)((char*)g_w2l + off) = l;
    }
}

// ---------------- x fp32 -> split bf16 ----------------
__global__ void xcvt_kernel(const float* __restrict__ x) {
    int i = blockIdx.x * blockDim.x + threadIdx.x;
    const int n = BB * T_EN * C_IN;
    if (i < n) {
        __nv_bfloat16 h, l; split_bf16(x[i], h, l);
        g_xh[i] = h; g_xl[i] = l;
    }
}

// ---------------- duration cumsum + ty->tx map + src_len ----------------
__global__ void scan_kernel(const float* __restrict__ dur, int tde) {
    __shared__ float s[T_EN];
    __shared__ int cnt;
    int b = blockIdx.x, t = threadIdx.x;
    if (t == 0) cnt = 0;
    float d = dur[b * T_EN + t];
    s[t] = d;
    __syncthreads();
    if (d > 0.f) atomicAdd(&cnt, 1);
    for (int off = 1; off < T_EN; off <<= 1) {
        float v = s[t];
        if (t >= off) v += s[t - off];
        __syncthreads();
        s[t] = v;
        __syncthreads();
    }
    for (int y = t; y < tde; y += T_EN) g_txmap[b * T_DE_MAX + y] = -1;
    __syncthreads();
    if (d > 0.f) {
        int e  = (int)(s[t] + 0.5f);
        int st = (t > 0) ? (int)(s[t - 1] + 0.5f) : 0;
        for (int y = st; y < e && y < tde; y++) g_txmap[b * T_DE_MAX + y] = t;
    }
    if (t == 0) g_srclen[b] = cnt;
}

// ================= split-bf16 HMMA conv kernel: M=128 tile, N=256, K streamed 64-wide =================
// smem (from 1024-aligned base sb):
//   [0:4096)         params: bias | ln_g | ln_b | lw   (4 x 256 f32)
//   [4096:69632)     A bufs: 2 bufs x {hi,lo} x 16KB
//   [69632:200704)   B bufs: 2 bufs x {hi,lo} x 32KB
//   epilogue fp32 tile [128][258] reuses [4096:136192)
#define OFF_A 4096
#define OFF_B 69632
#define OFF_E 4096
#define EST   258
#define CONV_SMEM (200704 + 1024)

template<int CCH, bool IS2>
__global__ void __launch_bounds__(512, 1) mma_conv(
    const float* __restrict__ bias, const float* __restrict__ lng, const float* __restrict__ lnb,
    const float* __restrict__ lw, const float* __restrict__ lb, float* __restrict__ out2)
{
    constexpr int S = 5 * (CCH / 64);
    extern __shared__ char smem_raw[];
    const uint32_t sb = (smem_u32(smem_raw) + 1023u) & ~1023u;
    char* sbp = smem_raw + (sb - smem_u32(smem_raw));
    const int tid = threadIdx.x, wid = tid >> 5, lane = tid & 31;
    const int b = blockIdx.y, t0 = blockIdx.x * 128;
    const int sl = g_srclen[b];
    if (!IS2) {
        if (t0 > sl + 1) return;
    } else {
        if (t0 >= sl) { if (tid < 128) out2[(size_t)b * T_EN + t0 + tid] = 0.f; return; }
    }
    const __nv_bfloat16* __restrict__ xh = IS2 ? g_h1h : g_xh;
    const __nv_bfloat16* __restrict__ xl = IS2 ? g_h1l : g_xl;
    const char* __restrict__ wh = IS2 ? (const char*)g_w2h : (const char*)g_w1h;
    const char* __restrict__ wl = IS2 ? (const char*)g_w2l : (const char*)g_w1l;

    float* ps = (float*)sbp;
    if (tid < 256) {
        ps[tid]       = bias[tid];
        ps[256 + tid] = lng[tid];
        ps[512 + tid] = lnb[tid];
        ps[768 + tid] = IS2 ? lw[tid] : 0.f;
    }

    auto load_stage = [&](int s, int buf) {
        const int k = s / (CCH / 64), cb = s % (CCH / 64);
        // B tiles (hi, lo)
        const char* bsh = wh + (size_t)s * 32768;
        const char* bsl = wl + (size_t)s * 32768;
        uint32_t bb_h = sb + OFF_B + buf * 65536;
        uint32_t bb_l = bb_h + 32768;
#pragma unroll
        for (int i = 0; i < 4; i++) {
            int seg = tid + i * 512;
            cp16(bb_h + seg * 16, bsh + seg * 16);
            cp16(bb_l + seg * 16, bsl + seg * 16);
        }
        // A tiles (hi, lo), im2col shift by k-2
        uint32_t ab_h = sb + OFF_A + buf * 32768;
        uint32_t ab_l = ab_h + 16384;
        const __nv_bfloat16* xh0 = xh + (size_t)b * T_EN * CCH + cb * 64;
        const __nv_bfloat16* xl0 = xl + (size_t)b * T_EN * CCH + cb * 64;
#pragma unroll
        for (int i = 0; i < 2; i++) {
            int seg = tid + i * 512;
            int r = seg >> 3, c8 = seg & 7;
            int t = t0 + r + k - 2;
            uint32_t sw = SW128((uint32_t)(r * 128 + c8 * 16));
            if ((unsigned)t < T_EN) {
                cp16(ab_h + sw, (const char*)(xh0 + (size_t)t * CCH + c8 * 8));
                cp16(ab_l + sw, (const char*)(xl0 + (size_t)t * CCH + c8 * 8));
            } else {
                asm volatile("st.shared.v4.b32 [%0], {%1, %1, %1, %1};" :: "r"(ab_h + sw), "r"(0u) : "memory");
                asm volatile("st.shared.v4.b32 [%0], {%1, %1, %1, %1};" :: "r"(ab_l + sw), "r"(0u) : "memory");
            }
        }
    };

    // warp layout: 4 (M) x 4 (N); warp tile 32 x 64
    const int wm = wid & 3, wn = wid >> 2;
    const int lr = lane & 7, g = lane >> 3;
    const int rA0 = wm * 32 + lr + ((g & 1) << 3);
    const int kA  = ((g >> 1) & 1) << 4;
    const int rB0 = wn * 64 + lr + (((g >> 1) & 1) << 3);
    const int kB  = (g & 1) << 4;

    float acc[2][8][4];
#pragma unroll
    for (int mt = 0; mt < 2; mt++)
#pragma unroll
        for (int j = 0; j < 8; j++)
#pragma unroll
            for (int q = 0; q < 4; q++) acc[mt][j][q] = 0.f;

    load_stage(0, 0);
    cpcommit();
    for (int s = 0; s < S; s++) {
        int buf = s & 1;
        if (s + 1 < S) { load_stage(s + 1, buf ^ 1); cpcommit(); cpwait<1>(); }
        else cpwait<0>();
        __syncthreads();

        const uint32_t ab_h = sb + OFF_A + buf * 32768;
        const uint32_t ab_l = ab_h + 16384;
        const uint32_t bb_h = sb + OFF_B + buf * 65536;
        const uint32_t bb_l = bb_h + 32768;
#pragma unroll
        for (int kk = 0; kk < 4; kk++) {
            uint32_t Ah[2][4], Al[2][4];
#pragma unroll
            for (int mt = 0; mt < 2; mt++) {
                int row = rA0 + mt * 16;
                uint32_t off = row * 128 + (uint32_t)((kk * 32 + kA) ^ ((row & 7) << 4));
                ldsm4(Ah[mt], ab_h + off);
                ldsm4(Al[mt], ab_l + off);
            }
#pragma unroll
            for (int nt = 0; nt < 4; nt++) {
                int row = rB0 + nt * 16;
                uint32_t off = row * 128 + (uint32_t)((kk * 32 + kB) ^ ((row & 7) << 4));
                uint32_t Bf[4];
                ldsm4(Bf, bb_h + off);
#pragma unroll
                for (int mt = 0; mt < 2; mt++) {
                    mma16816(acc[mt][2 * nt],     Ah[mt], Bf[0], Bf[1]);
                    mma16816(acc[mt][2 * nt + 1], Ah[mt], Bf[2], Bf[3]);
                    mma16816(acc[mt][2 * nt],     Al[mt], Bf[0], Bf[1]);
                    mma16816(acc[mt][2 * nt + 1], Al[mt], Bf[2], Bf[3]);
                }
                ldsm4(Bf, bb_l + off);
#pragma unroll
                for (int mt = 0; mt < 2; mt++) {
                    mma16816(acc[mt][2 * nt],     Ah[mt], Bf[0], Bf[1]);
                    mma16816(acc[mt][2 * nt + 1], Ah[mt], Bf[2], Bf[3]);
                }
            }
        }
        __syncthreads();
    }

    // ---- epilogue: accs -> smem fp32 tile, then per-row LN ----
    float* es = (float*)(sbp + OFF_E);
#pragma unroll
    for (int mt = 0; mt < 2; mt++) {
        int r0 = wm * 32 + mt * 16 + (lane >> 2);
#pragma unroll
        for (int j = 0; j < 8; j++) {
            int cc = wn * 64 + j * 8 + (lane & 3) * 2;
            *(float2*)&es[(size_t)r0 * EST + cc]       = make_float2(acc[mt][j][0], acc[mt][j][1]);
            *(float2*)&es[(size_t)(r0 + 8) * EST + cc] = make_float2(acc[mt][j][2], acc[mt][j][3]);
        }
    }
    __syncthreads();

#pragma unroll
    for (int i = 0; i < 8; i++) {
        int row = wid * 8 + i;
        float v[8], sum = 0.f, sq = 0.f;
#pragma unroll
        for (int k = 0; k < 8; k++) {
            int c = lane + 32 * k;
            float x = fmaxf(es[(size_t)row * EST + c] + ps[c], 0.f);
            v[k] = x; sum += x; sq += x * x;
        }
#pragma unroll
        for (int o = 16; o; o >>= 1) {
            sum += __shfl_xor_sync(0xffffffffu, sum, o);
            sq  += __shfl_xor_sync(0xffffffffu, sq,  o);
        }
        float m  = sum * (1.f / 256.f);
        float rv = rsqrtf(sq * (1.f / 256.f) - m * m + 1e-5f);
        if (!IS2) {
            __nv_bfloat16* hrow = g_h1h + ((size_t)b * T_EN + (t0 + row)) * C_H;
            __nv_bfloat16* lrow = g_h1l + ((size_t)b * T_EN + (t0 + row)) * C_H;
#pragma unroll
            for (int k = 0; k < 8; k++) {
                int c = lane + 32 * k;
                float n = (v[k] - m) * rv * ps[256 + c] + ps[512 + c];
                __nv_bfloat16 h, l; split_bf16(n, h, l);
                hrow[c] = h; lrow[c] = l;
            }
        } else {
            float dot = 0.f;
#pragma unroll
            for (int k = 0; k < 8; k++) {
                int c = lane + 32 * k;
                float n = (v[k] - m) * rv * ps[256 + c] + ps[512 + c];
                dot += n * ps[768 + c];
            }
#pragma unroll
            for (int o = 16; o; o >>= 1) dot += __shfl_xor_sync(0xffffffffu, dot, o);
            if (lane == 0) {
                int t = t0 + row;
                out2[(size_t)b * T_EN + t] = (t < sl) ? (dot + lb[0]) : 0.f;
            }
        }
    }
}

// ---------------- scatter ones into attn^T ----------------
__global__ void ones_kernel(float* __restrict__ out4, int tde) {
    int i = blockIdx.x * blockDim.x + threadIdx.x;
    if (i >= BB * tde) return;
    int b = i / tde, ty = i % tde;
    int tx = g_txmap[b * T_DE_MAX + ty];
    if (tx >= 0) out4[((size_t)b * tde + ty) * T_EN + tx] = 1.0f;
}

// ---------------- encoder_output gather: out3[b][c][ty] = enc[b][tx(ty)][c] ----------------
__global__ void gather3_kernel(const float* __restrict__ enc, float* __restrict__ out3, int tde) {
    int b = blockIdx.y;
    int ty = blockIdx.x * 256 + threadIdx.x;
    if (ty >= tde) return;
    int tx = g_txmap[b * T_DE_MAX + ty];
    float* ob = out3 + (size_t)b * C_IN * tde + ty;
    if (tx < 0) {
        for (int c = 0; c < C_IN; c++) ob[(size_t)c * tde] = 0.f;
    } else {
        const float4* e4 = (const float4*)(enc + ((size_t)b * T_EN + tx) * C_IN);
        for (int c4 = 0; c4 < C_IN / 4; c4++) {
            float4 v = e4[c4];
            ob[(size_t)(4 * c4 + 0) * tde] = v.x;
            ob[(size_t)(4 * c4 + 1) * tde] = v.y;
            ob[(size_t)(4 * c4 + 2) * tde] = v.z;
            ob[(size_t)(4 * c4 + 3) * tde] = v.w;
        }
    }
}

// ---------------- launcher ----------------
extern "C" void kernel_launch(void* const* d_in, const int* in_sizes, int n_in,
                              void* d_out, int out_size) {
    const float* enc    = (const float*)d_in[0];
    const float* encres = (const float*)d_in[1];
    const float* dur    = (const float*)d_in[2];
    const float* c1w    = (const float*)d_in[3];
    const float* c1b    = (const float*)d_in[4];
    const float* g1     = (const float*)d_in[5];
    const float* b1     = (const float*)d_in[6];
    const float* c2w    = (const float*)d_in[7];
    const float* c2b    = (const float*)d_in[8];
    const float* g2     = (const float*)d_in[9];
    const float* b2     = (const float*)d_in[10];
    const float* lw     = (const float*)d_in[11];
    const float* lb     = (const float*)d_in[12];

    float* out = (float*)d_out;
    int tde = (int)(((long long)out_size - (long long)BB * T_EN) /
                    (2LL * BB * T_EN + (long long)BB * C_IN));
    if (tde <= 0 || tde > T_DE_MAX) return;

    float* out1 = out;                                    // [B, T_EN, T_DE] zeros
    float* out2 = out1 + (size_t)BB * T_EN * tde;         // [B, T_EN]
    float* out3 = out2 + (size_t)BB * T_EN;               // [B, C_IN, T_DE]
    float* out4 = out3 + (size_t)BB * C_IN * tde;         // [B, T_DE, T_EN]

    cudaFuncSetAttribute(mma_conv<C_IN, false>, cudaFuncAttributeMaxDynamicSharedMemorySize, CONV_SMEM);
    cudaFuncSetAttribute(mma_conv<C_H,  true >, cudaFuncAttributeMaxDynamicSharedMemorySize, CONV_SMEM);

    cudaMemsetAsync(out1, 0, (size_t)BB * T_EN * tde * sizeof(float));
    cudaMemsetAsync(out4, 0, (size_t)BB * T_EN * tde * sizeof(float));

    wtb_kernel<<<512, 256>>>(c1w, c2w);
    xcvt_kernel<<<(BB * T_EN * C_IN + 255) / 256, 256>>>(encres);
    scan_kernel<<<BB, T_EN>>>(dur, tde);

    mma_conv<C_IN, false><<<dim3(T_EN / 128, BB), 512, CONV_SMEM>>>(c1b, g1, b1, lw, lb, nullptr);
    mma_conv<C_H,  true ><<<dim3(T_EN / 128, BB), 512, CONV_SMEM>>>(c2b, g2, b2, lw, lb, out2);

    ones_kernel<<<(BB * tde + 255) / 256, 256>>>(out4, tde);
    gather3_kernel<<<dim3((tde + 255) / 256, BB), 256>>>(enc, out3, tde);
}

// round 13
// speedup vs baseline: 5.0622x; 1.0220x over previous
#include <cuda_runtime.h>
#include <cuda_bf16.h>
#include <cstdint>
#include <cstddef>

#define BB    16
#define T_EN  1024
#define C_IN  512
#define C_H   256
#define KSZ   5
#define T_DE_MAX 3072

typedef unsigned long long ull;

// ---------------- device scratch (no runtime allocation allowed) ----------------
// split-bf16 representation: value = hi + lo, hi = bf16(v), lo = bf16(v - hi)
__device__ __nv_bfloat16 g_xh [(size_t)BB * T_EN * C_IN];
__device__ __nv_bfloat16 g_xl [(size_t)BB * T_EN * C_IN];
__device__ __nv_bfloat16 g_h1h[(size_t)BB * T_EN * C_H];
__device__ __nv_bfloat16 g_h1l[(size_t)BB * T_EN * C_H];
// pre-swizzled B-operand stage blocks: stage = k*(CCH/64)+ci/64, block = [co 0..255][64 k-cols] SW128
__device__ __nv_bfloat16 g_w1h[40 * 16384];
__device__ __nv_bfloat16 g_w1l[40 * 16384];
__device__ __nv_bfloat16 g_w2h[20 * 16384];
__device__ __nv_bfloat16 g_w2l[20 * 16384];
__device__ int g_txmap[BB * T_DE_MAX];
__device__ int g_srclen[BB];

// ---------------- PTX helpers (portable: sm_80+) ----------------
__device__ __forceinline__ uint32_t smem_u32(const void* p) {
    uint32_t a;
    asm("{ .reg .u64 t; cvta.to.shared.u64 t, %1; cvt.u32.u64 %0, t; }" : "=r"(a) : "l"(p));
    return a;
}
#define SW128(o) ((o) ^ (((o) >> 3) & 0x70))

__device__ __forceinline__ void cp16(uint32_t dst, const void* src) {
    asm volatile("cp.async.cg.shared.global [%0], [%1], 16;" :: "r"(dst), "l"(src) : "memory");
}
__device__ __forceinline__ void cpcommit() { asm volatile("cp.async.commit_group;" ::: "memory"); }
template<int N>
__device__ __forceinline__ void cpwait() { asm volatile("cp.async.wait_group %0;" :: "n"(N) : "memory"); }

__device__ __forceinline__ void ldsm4(uint32_t* f, uint32_t addr) {
    asm volatile("ldmatrix.sync.aligned.m8n8.x4.shared.b16 {%0, %1, %2, %3}, [%4];"
                 : "=r"(f[0]), "=r"(f[1]), "=r"(f[2]), "=r"(f[3]) : "r"(addr));
}
__device__ __forceinline__ void mma16816(float* c, const uint32_t* a, uint32_t b0, uint32_t b1) {
    asm("mma.sync.aligned.m16n8k16.row.col.f32.bf16.bf16.f32 "
        "{%0, %1, %2, %3}, {%4, %5, %6, %7}, {%8, %9}, {%0, %1, %2, %3};"
        : "+f"(c[0]), "+f"(c[1]), "+f"(c[2]), "+f"(c[3])
        : "r"(a[0]), "r"(a[1]), "r"(a[2]), "r"(a[3]), "r"(b0), "r"(b1));
}

__device__ __forceinline__ void split_bf16(float v, __nv_bfloat16& h, __nv_bfloat16& l) {
    h = __float2bfloat16(v);
    l = __float2bfloat16(v - __bfloat162float(h));
}

// ---------------- fused prep: weights -> split-bf16 swizzled stages; x -> split-bf16 ----------------
__global__ void prep_kernel(const float* __restrict__ w1, const float* __restrict__ w2,
                            const float* __restrict__ x) {
    const int n1 = C_H * C_IN * KSZ;
    for (int i = blockIdx.x * blockDim.x + threadIdx.x; i < n1; i += gridDim.x * blockDim.x) {
        int k  = i % KSZ;
        int ci = (i / KSZ) % C_IN;
        int co = i / (KSZ * C_IN);
        int stage = k * (C_IN / 64) + (ci >> 6);
        int col = ci & 63;
        size_t off = (size_t)stage * 32768 + SW128((uint32_t)(co * 128 + col * 2));
        __nv_bfloat16 h, l; split_bf16(w1[i], h, l);
        *(__nv_bfloat16*)((char*)g_w1h + off) = h;
        *(__nv_bfloat16*)((char*)g_w1l + off) = l;
    }
    const int n2 = C_H * C_H * KSZ;
    for (int i = blockIdx.x * blockDim.x + threadIdx.x; i < n2; i += gridDim.x * blockDim.x) {
        int k  = i % KSZ;
        int ci = (i / KSZ) % C_H;
        int co = i / (KSZ * C_H);
        int stage = k * (C_H / 64) + (ci >> 6);
        int col = ci & 63;
        size_t off = (size_t)stage * 32768 + SW128((uint32_t)(co * 128 + col * 2));
        __nv_bfloat16 h, l; split_bf16(w2[i], h, l);
        *(__nv_bfloat16*)((char*)g_w2h + off) = h;
        *(__nv_bfloat16*)((char*)g_w2l + off) = l;
    }
    const int n3 = BB * T_EN * C_IN;
    for (int i = blockIdx.x * blockDim.x + threadIdx.x; i < n3; i += gridDim.x * blockDim.x) {
        __nv_bfloat16 h, l; split_bf16(x[i], h, l);
        g_xh[i] = h; g_xl[i] = l;
    }
}

// ---------------- duration cumsum + ty->tx map + src_len ----------------
__global__ void scan_kernel(const float* __restrict__ dur, int tde) {
    __shared__ float s[T_EN];
    __shared__ int cnt;
    int b = blockIdx.x, t = threadIdx.x;
    if (t == 0) cnt = 0;
    float d = dur[b * T_EN + t];
    s[t] = d;
    __syncthreads();
    if (d > 0.f) atomicAdd(&cnt, 1);
    for (int off = 1; off < T_EN; off <<= 1) {
        float v = s[t];
        if (t >= off) v += s[t - off];
        __syncthreads();
        s[t] = v;
        __syncthreads();
    }
    for (int y = t; y < tde; y += T_EN) g_txmap[b * T_DE_MAX + y] = -1;
    __syncthreads();
    if (d > 0.f) {
        int e  = (int)(s[t] + 0.5f);
        int st = (t > 0) ? (int)(s[t - 1] + 0.5f) : 0;
        for (int y = st; y < e && y < tde; y++) g_txmap[b * T_DE_MAX + y] = t;
    }
    if (t == 0) g_srclen[b] = cnt;
}

// ================= split-bf16 HMMA conv kernel: M=128 tile, N=256, K streamed 64-wide =================
// smem (from 1024-aligned base sb):
//   [0:4096)         params: bias | ln_g | ln_b | lw   (4 x 256 f32)
//   [4096:69632)     A bufs: 2 bufs x {hi,lo} x 16KB
//   [69632:200704)   B bufs: 2 bufs x {hi,lo} x 32KB
//   epilogue fp32 tile [128][258] reuses [4096:136192)
#define OFF_A 4096
#define OFF_B 69632
#define OFF_E 4096
#define EST   258
#define CONV_SMEM (200704 + 1024)

template<int CCH, bool IS2>
__global__ void __launch_bounds__(512, 1) mma_conv(
    const float* __restrict__ bias, const float* __restrict__ lng, const float* __restrict__ lnb,
    const float* __restrict__ lw, const float* __restrict__ lb, float* __restrict__ out2)
{
    constexpr int S = 5 * (CCH / 64);
    extern __shared__ char smem_raw[];
    const uint32_t sb = (smem_u32(smem_raw) + 1023u) & ~1023u;
    char* sbp = smem_raw + (sb - smem_u32(smem_raw));
    const int tid = threadIdx.x, wid = tid >> 5, lane = tid & 31;
    const int b = blockIdx.y, t0 = blockIdx.x * 128;
    const int sl = g_srclen[b];
    if (!IS2) {
        if (t0 > sl + 1) return;
    } else {
        if (t0 >= sl) { if (tid < 128) out2[(size_t)b * T_EN + t0 + tid] = 0.f; return; }
    }
    const __nv_bfloat16* __restrict__ xh = IS2 ? g_h1h : g_xh;
    const __nv_bfloat16* __restrict__ xl = IS2 ? g_h1l : g_xl;
    const char* __restrict__ wh = IS2 ? (const char*)g_w2h : (const char*)g_w1h;
    const char* __restrict__ wl = IS2 ? (const char*)g_w2l : (const char*)g_w1l;

    float* ps = (float*)sbp;
    if (tid < 256) {
        ps[tid]       = bias[tid];
        ps[256 + tid] = lng[tid];
        ps[512 + tid] = lnb[tid];
        ps[768 + tid] = IS2 ? lw[tid] : 0.f;
    }

    auto load_stage = [&](int s, int buf) {
        const int k = s / (CCH / 64), cb = s % (CCH / 64);
        const char* bsh = wh + (size_t)s * 32768;
        const char* bsl = wl + (size_t)s * 32768;
        uint32_t bb_h = sb + OFF_B + buf * 65536;
        uint32_t bb_l = bb_h + 32768;
#pragma unroll
        for (int i = 0; i < 4; i++) {
            int seg = tid + i * 512;
            cp16(bb_h + seg * 16, bsh + seg * 16);
            cp16(bb_l + seg * 16, bsl + seg * 16);
        }
        uint32_t ab_h = sb + OFF_A + buf * 32768;
        uint32_t ab_l = ab_h + 16384;
        const __nv_bfloat16* xh0 = xh + (size_t)b * T_EN * CCH + cb * 64;
        const __nv_bfloat16* xl0 = xl + (size_t)b * T_EN * CCH + cb * 64;
#pragma unroll
        for (int i = 0; i < 2; i++) {
            int seg = tid + i * 512;
            int r = seg >> 3, c8 = seg & 7;
            int t = t0 + r + k - 2;
            uint32_t sw = SW128((uint32_t)(r * 128 + c8 * 16));
            if ((unsigned)t < T_EN) {
                cp16(ab_h + sw, (const char*)(xh0 + (size_t)t * CCH + c8 * 8));
                cp16(ab_l + sw, (const char*)(xl0 + (size_t)t * CCH + c8 * 8));
            } else {
                asm volatile("st.shared.v4.b32 [%0], {%1, %1, %1, %1};" :: "r"(ab_h + sw), "r"(0u) : "memory");
                asm volatile("st.shared.v4.b32 [%0], {%1, %1, %1, %1};" :: "r"(ab_l + sw), "r"(0u) : "memory");
            }
        }
    };

    // warp layout: 4 (M) x 4 (N); warp tile 32 x 64
    const int wm = wid & 3, wn = wid >> 2;
    const int lr = lane & 7, g = lane >> 3;
    const int rA0 = wm * 32 + lr + ((g & 1) << 3);
    const int kA  = ((g >> 1) & 1) << 4;
    const int rB0 = wn * 64 + lr + (((g >> 1) & 1) << 3);
    const int kB  = (g & 1) << 4;

    float acc[2][8][4];
#pragma unroll
    for (int mt = 0; mt < 2; mt++)
#pragma unroll
        for (int j = 0; j < 8; j++)
#pragma unroll
            for (int q = 0; q < 4; q++) acc[mt][j][q] = 0.f;

    load_stage(0, 0);
    cpcommit();
    for (int s = 0; s < S; s++) {
        int buf = s & 1;
        if (s + 1 < S) { load_stage(s + 1, buf ^ 1); cpcommit(); cpwait<1>(); }
        else cpwait<0>();
        __syncthreads();

        const uint32_t ab_h = sb + OFF_A + buf * 32768;
        const uint32_t ab_l = ab_h + 16384;
        const uint32_t bb_h = sb + OFF_B + buf * 65536;
        const uint32_t bb_l = bb_h + 32768;
#pragma unroll
        for (int kk = 0; kk < 4; kk++) {
            uint32_t Ah[2][4], Al[2][4];
#pragma unroll
            for (int mt = 0; mt < 2; mt++) {
                int row = rA0 + mt * 16;
                uint32_t off = row * 128 + (uint32_t)((kk * 32 + kA) ^ ((row & 7) << 4));
                ldsm4(Ah[mt], ab_h + off);
                ldsm4(Al[mt], ab_l + off);
            }
#pragma unroll
            for (int nt = 0; nt < 4; nt++) {
                int row = rB0 + nt * 16;
                uint32_t off = row * 128 + (uint32_t)((kk * 32 + kB) ^ ((row & 7) << 4));
                uint32_t Bh[4], Bl[4];                 // separate reg sets: no WAR serialization
                ldsm4(Bh, bb_h + off);
                ldsm4(Bl, bb_l + off);
                // 12 MMAs as 4 independent chains, deps 4 issues apart
                mma16816(acc[0][2 * nt],     Ah[0], Bh[0], Bh[1]);
                mma16816(acc[0][2 * nt + 1], Ah[0], Bh[2], Bh[3]);
                mma16816(acc[1][2 * nt],     Ah[1], Bh[0], Bh[1]);
                mma16816(acc[1][2 * nt + 1], Ah[1], Bh[2], Bh[3]);
                mma16816(acc[0][2 * nt],     Al[0], Bh[0], Bh[1]);
                mma16816(acc[0][2 * nt + 1], Al[0], Bh[2], Bh[3]);
                mma16816(acc[1][2 * nt],     Al[1], Bh[0], Bh[1]);
                mma16816(acc[1][2 * nt + 1], Al[1], Bh[2], Bh[3]);
                mma16816(acc[0][2 * nt],     Ah[0], Bl[0], Bl[1]);
                mma16816(acc[0][2 * nt + 1], Ah[0], Bl[2], Bl[3]);
                mma16816(acc[1][2 * nt],     Ah[1], Bl[0], Bl[1]);
                mma16816(acc[1][2 * nt + 1], Ah[1], Bl[2], Bl[3]);
            }
        }
        __syncthreads();
    }

    // ---- epilogue: accs -> smem fp32 tile, then per-row LN ----
    float* es = (float*)(sbp + OFF_E);
#pragma unroll
    for (int mt = 0; mt < 2; mt++) {
        int r0 = wm * 32 + mt * 16 + (lane >> 2);
#pragma unroll
        for (int j = 0; j < 8; j++) {
            int cc = wn * 64 + j * 8 + (lane & 3) * 2;
            *(float2*)&es[(size_t)r0 * EST + cc]       = make_float2(acc[mt][j][0], acc[mt][j][1]);
            *(float2*)&es[(size_t)(r0 + 8) * EST + cc] = make_float2(acc[mt][j][2], acc[mt][j][3]);
        }
    }
    __syncthreads();

#pragma unroll
    for (int i = 0; i < 8; i++) {
        int row = wid * 8 + i;
        float v[8], sum = 0.f, sq = 0.f;
#pragma unroll
        for (int k = 0; k < 8; k++) {
            int c = lane + 32 * k;
            float x = fmaxf(es[(size_t)row * EST + c] + ps[c], 0.f);
            v[k] = x; sum += x; sq += x * x;
        }
#pragma unroll
        for (int o = 16; o; o >>= 1) {
            sum += __shfl_xor_sync(0xffffffffu, sum, o);
            sq  += __shfl_xor_sync(0xffffffffu, sq,  o);
        }
        float m  = sum * (1.f / 256.f);
        float rv = rsqrtf(sq * (1.f / 256.f) - m * m + 1e-5f);
        if (!IS2) {
            __nv_bfloat16* hrow = g_h1h + ((size_t)b * T_EN + (t0 + row)) * C_H;
            __nv_bfloat16* lrow = g_h1l + ((size_t)b * T_EN + (t0 + row)) * C_H;
#pragma unroll
            for (int k = 0; k < 8; k++) {
                int c = lane + 32 * k;
                float n = (v[k] - m) * rv * ps[256 + c] + ps[512 + c];
                __nv_bfloat16 h, l; split_bf16(n, h, l);
                hrow[c] = h; lrow[c] = l;
            }
        } else {
            float dot = 0.f;
#pragma unroll
            for (int k = 0; k < 8; k++) {
                int c = lane + 32 * k;
                float n = (v[k] - m) * rv * ps[256 + c] + ps[512 + c];
                dot += n * ps[768 + c];
            }
#pragma unroll
            for (int o = 16; o; o >>= 1) dot += __shfl_xor_sync(0xffffffffu, dot, o);
            if (lane == 0) {
                int t = t0 + row;
                out2[(size_t)b * T_EN + t] = (t < sl) ? (dot + lb[0]) : 0.f;
            }
        }
    }
}

// ---------------- scatter ones into attn^T ----------------
__global__ void ones_kernel(float* __restrict__ out4, int tde) {
    int i = blockIdx.x * blockDim.x + threadIdx.x;
    if (i >= BB * tde) return;
    int b = i / tde, ty = i % tde;
    int tx = g_txmap[b * T_DE_MAX + ty];
    if (tx >= 0) out4[((size_t)b * tde + ty) * T_EN + tx] = 1.0f;
}

// ---------------- encoder_output gather: out3[b][c][ty] = enc[b][tx(ty)][c] ----------------
__global__ void gather3_kernel(const float* __restrict__ enc, float* __restrict__ out3, int tde) {
    int b = blockIdx.y;
    int ty = blockIdx.x * 256 + threadIdx.x;
    if (ty >= tde) return;
    int tx = g_txmap[b * T_DE_MAX + ty];
    float* ob = out3 + (size_t)b * C_IN * tde + ty;
    if (tx < 0) {
        for (int c = 0; c < C_IN; c++) ob[(size_t)c * tde] = 0.f;
    } else {
        const float4* e4 = (const float4*)(enc + ((size_t)b * T_EN + tx) * C_IN);
        for (int c4 = 0; c4 < C_IN / 4; c4++) {
            float4 v = e4[c4];
            ob[(size_t)(4 * c4 + 0) * tde] = v.x;
            ob[(size_t)(4 * c4 + 1) * tde] = v.y;
            ob[(size_t)(4 * c4 + 2) * tde] = v.z;
            ob[(size_t)(4 * c4 + 3) * tde] = v.w;
        }
    }
}

// ---------------- launcher ----------------
extern "C" void kernel_launch(void* const* d_in, const int* in_sizes, int n_in,
                              void* d_out, int out_size) {
    const float* enc    = (const float*)d_in[0];
    const float* encres = (const float*)d_in[1];
    const float* dur    = (const float*)d_in[2];
    const float* c1w    = (const float*)d_in[3];
    const float* c1b    = (const float*)d_in[4];
    const float* g1     = (const float*)d_in[5];
    const float* b1     = (const float*)d_in[6];
    const float* c2w    = (const float*)d_in[7];
    const float* c2b    = (const float*)d_in[8];
    const float* g2     = (const float*)d_in[9];
    const float* b2     = (const float*)d_in[10];
    const float* lw     = (const float*)d_in[11];
    const float* lb     = (const float*)d_in[12];

    float* out = (float*)d_out;
    int tde = (int)(((long long)out_size - (long long)BB * T_EN) /
                    (2LL * BB * T_EN + (long long)BB * C_IN));
    if (tde <= 0 || tde > T_DE_MAX) return;

    float* out1 = out;                                    // [B, T_EN, T_DE] zeros
    float* out2 = out1 + (size_t)BB * T_EN * tde;         // [B, T_EN]
    float* out3 = out2 + (size_t)BB * T_EN;               // [B, C_IN, T_DE]
    float* out4 = out3 + (size_t)BB * C_IN * tde;         // [B, T_DE, T_EN]

    cudaFuncSetAttribute(mma_conv<C_IN, false>, cudaFuncAttributeMaxDynamicSharedMemorySize, CONV_SMEM);
    cudaFuncSetAttribute(mma_conv<C_H,  true >, cudaFuncAttributeMaxDynamicSharedMemorySize, CONV_SMEM);

    cudaMemsetAsync(out1, 0, (size_t)BB * T_EN * tde * sizeof(float));
    cudaMemsetAsync(out4, 0, (size_t)BB * T_EN * tde * sizeof(float));

    prep_kernel<<<1024, 256>>>(c1w, c2w, encres);
    scan_kernel<<<BB, T_EN>>>(dur, tde);

    mma_conv<C_IN, false><<<dim3(T_EN / 128, BB), 512, CONV_SMEM>>>(c1b, g1, b1, lw, lb, nullptr);
    mma_conv<C_H,  true ><<<dim3(T_EN / 128, BB), 512, CONV_SMEM>>>(c2b, g2, b2, lw, lb, out2);

    ones_kernel<<<(BB * tde + 255) / 256, 256>>>(out4, tde);
    gather3_kernel<<<dim3((tde + 255) / 256, BB), 256>>>(enc, out3, tde);
}

// round 15
// speedup vs baseline: 5.3861x; 1.0640x over previous
#include <cuda_runtime.h>
#include <cuda_bf16.h>
#include <cstdint>
#include <cstddef>

#define BB    16
#define T_EN  1024
#define C_IN  512
#define C_H   256
#define KSZ   5
#define T_DE_MAX 3072

typedef unsigned long long ull;

// ---------------- device scratch (no runtime allocation allowed) ----------------
// split-bf16 representation: value = hi + lo, hi = bf16(v), lo = bf16(v - hi)
__device__ __nv_bfloat16 g_xh [(size_t)BB * T_EN * C_IN];
__device__ __nv_bfloat16 g_xl [(size_t)BB * T_EN * C_IN];
__device__ __nv_bfloat16 g_h1h[(size_t)BB * T_EN * C_H];
__device__ __nv_bfloat16 g_h1l[(size_t)BB * T_EN * C_H];
__device__ float g_cv[(size_t)BB * T_EN * C_H];          // raw conv GEMM output (fp32)
// pre-swizzled B-operand stage blocks: stage = k*(CCH/64)+ci/64, block = [co 0..255][64 k-cols] SW128
__device__ __nv_bfloat16 g_w1h[40 * 16384];
__device__ __nv_bfloat16 g_w1l[40 * 16384];
__device__ __nv_bfloat16 g_w2h[20 * 16384];
__device__ __nv_bfloat16 g_w2l[20 * 16384];
__device__ int g_txmap[BB * T_DE_MAX];
__device__ int g_srclen[BB];

// ---------------- PTX helpers (portable: sm_80+) ----------------
__device__ __forceinline__ uint32_t smem_u32(const void* p) {
    uint32_t a;
    asm("{ .reg .u64 t; cvta.to.shared.u64 t, %1; cvt.u32.u64 %0, t; }" : "=r"(a) : "l"(p));
    return a;
}
#define SW128(o) ((o) ^ (((o) >> 3) & 0x70))

__device__ __forceinline__ void cp16(uint32_t dst, const void* src) {
    asm volatile("cp.async.cg.shared.global [%0], [%1], 16;" :: "r"(dst), "l"(src) : "memory");
}
__device__ __forceinline__ void cpcommit() { asm volatile("cp.async.commit_group;" ::: "memory"); }
template<int N>
__device__ __forceinline__ void cpwait() { asm volatile("cp.async.wait_group %0;" :: "n"(N) : "memory"); }

__device__ __forceinline__ void ldsm4(uint32_t* f, uint32_t addr) {
    asm volatile("ldmatrix.sync.aligned.m8n8.x4.shared.b16 {%0, %1, %2, %3}, [%4];"
                 : "=r"(f[0]), "=r"(f[1]), "=r"(f[2]), "=r"(f[3]) : "r"(addr));
}
__device__ __forceinline__ void mma16816(float* c, const uint32_t* a, uint32_t b0, uint32_t b1) {
    asm("mma.sync.aligned.m16n8k16.row.col.f32.bf16.bf16.f32 "
        "{%0, %1, %2, %3}, {%4, %5, %6, %7}, {%8, %9}, {%0, %1, %2, %3};"
        : "+f"(c[0]), "+f"(c[1]), "+f"(c[2]), "+f"(c[3])
        : "r"(a[0]), "r"(a[1]), "r"(a[2]), "r"(a[3]), "r"(b0), "r"(b1));
}

__device__ __forceinline__ void split_bf16(float v, __nv_bfloat16& h, __nv_bfloat16& l) {
    h = __float2bfloat16(v);
    l = __float2bfloat16(v - __bfloat162float(h));
}

// ---------------- fused prep: weights -> split-bf16 swizzled stages; x -> split-bf16 ----------------
__global__ void prep_kernel(const float* __restrict__ w1, const float* __restrict__ w2,
                            const float* __restrict__ x) {
    const int n1 = C_H * C_IN * KSZ;
    for (int i = blockIdx.x * blockDim.x + threadIdx.x; i < n1; i += gridDim.x * blockDim.x) {
        int k  = i % KSZ;
        int ci = (i / KSZ) % C_IN;
        int co = i / (KSZ * C_IN);
        int stage = k * (C_IN / 64) + (ci >> 6);
        int col = ci & 63;
        size_t off = (size_t)stage * 32768 + SW128((uint32_t)(co * 128 + col * 2));
        __nv_bfloat16 h, l; split_bf16(w1[i], h, l);
        *(__nv_bfloat16*)((char*)g_w1h + off) = h;
        *(__nv_bfloat16*)((char*)g_w1l + off) = l;
    }
    const int n2 = C_H * C_H * KSZ;
    for (int i = blockIdx.x * blockDim.x + threadIdx.x; i < n2; i += gridDim.x * blockDim.x) {
        int k  = i % KSZ;
        int ci = (i / KSZ) % C_H;
        int co = i / (KSZ * C_H);
        int stage = k * (C_H / 64) + (ci >> 6);
        int col = ci & 63;
        size_t off = (size_t)stage * 32768 + SW128((uint32_t)(co * 128 + col * 2));
        __nv_bfloat16 h, l; split_bf16(w2[i], h, l);
        *(__nv_bfloat16*)((char*)g_w2h + off) = h;
        *(__nv_bfloat16*)((char*)g_w2l + off) = l;
    }
    const int n3 = BB * T_EN * C_IN;
    for (int i = blockIdx.x * blockDim.x + threadIdx.x; i < n3; i += gridDim.x * blockDim.x) {
        __nv_bfloat16 h, l; split_bf16(x[i], h, l);
        g_xh[i] = h; g_xl[i] = l;
    }
}

// ---------------- duration cumsum + ty->tx map + src_len ----------------
__global__ void scan_kernel(const float* __restrict__ dur, int tde) {
    __shared__ float s[T_EN];
    __shared__ int cnt;
    int b = blockIdx.x, t = threadIdx.x;
    if (t == 0) cnt = 0;
    float d = dur[b * T_EN + t];
    s[t] = d;
    __syncthreads();
    if (d > 0.f) atomicAdd(&cnt, 1);
    for (int off = 1; off < T_EN; off <<= 1) {
        float v = s[t];
        if (t >= off) v += s[t - off];
        __syncthreads();
        s[t] = v;
        __syncthreads();
    }
    for (int y = t; y < tde; y += T_EN) g_txmap[b * T_DE_MAX + y] = -1;
    __syncthreads();
    if (d > 0.f) {
        int e  = (int)(s[t] + 0.5f);
        int st = (t > 0) ? (int)(s[t - 1] + 0.5f) : 0;
        for (int y = st; y < e && y < tde; y++) g_txmap[b * T_DE_MAX + y] = t;
    }
    if (t == 0) g_srclen[b] = cnt;
}

// ================= split-bf16 HMMA conv: M=64 x N=128 tiles, 2 CTAs/SM, raw fp32 out =================
// smem (from 1024-aligned base sb):
//   [0:32768)      A bufs: 2 bufs x {hi 8KB, lo 8KB}
//   [32768:98304)  B bufs: 2 bufs x {hi 16KB, lo 16KB}
#define OFF_B 32768
#define CONV_SMEM (98304 + 1024)

template<int CCH, bool IS2>
__global__ void __launch_bounds__(256, 2) mma_conv()
{
    constexpr int S = 5 * (CCH / 64);
    extern __shared__ char smem_raw[];
    const uint32_t sb = (smem_u32(smem_raw) + 1023u) & ~1023u;
    const int tid = threadIdx.x, wid = tid >> 5, lane = tid & 31;
    const int b = blockIdx.y, t0 = blockIdx.x * 64, nh = blockIdx.z;
    const int sl = g_srclen[b];
    if (!IS2) { if (t0 > sl + 1) return; }
    else      { if (t0 >= sl) return; }           // stale g_cv rows -> masked in ln2

    const __nv_bfloat16* __restrict__ xh = IS2 ? g_h1h : g_xh;
    const __nv_bfloat16* __restrict__ xl = IS2 ? g_h1l : g_xl;
    const char* __restrict__ wh = (IS2 ? (const char*)g_w2h : (const char*)g_w1h);
    const char* __restrict__ wl = (IS2 ? (const char*)g_w2l : (const char*)g_w1l);

    auto load_stage = [&](int s, int buf) {
        const int k = s / (CCH / 64), cb = s % (CCH / 64);
        const char* bsh = wh + (size_t)s * 32768 + nh * 16384;
        const char* bsl = wl + (size_t)s * 32768 + nh * 16384;
        uint32_t bb_h = sb + OFF_B + buf * 32768;
        uint32_t bb_l = bb_h + 16384;
#pragma unroll
        for (int i = 0; i < 4; i++) {
            int seg = tid + i * 256;
            cp16(bb_h + seg * 16, bsh + seg * 16);
            cp16(bb_l + seg * 16, bsl + seg * 16);
        }
        uint32_t ab_h = sb + buf * 16384;
        uint32_t ab_l = ab_h + 8192;
        const __nv_bfloat16* xh0 = xh + (size_t)b * T_EN * CCH + cb * 64;
        const __nv_bfloat16* xl0 = xl + (size_t)b * T_EN * CCH + cb * 64;
#pragma unroll
        for (int i = 0; i < 2; i++) {
            int seg = tid + i * 256;          // [0,512): 64 rows x 8 col-chunks
            int r = seg >> 3, c8 = seg & 7;
            int t = t0 + r + k - 2;
            uint32_t sw = SW128((uint32_t)(r * 128 + c8 * 16));
            if ((unsigned)t < T_EN) {
                cp16(ab_h + sw, (const char*)(xh0 + (size_t)t * CCH + c8 * 8));
                cp16(ab_l + sw, (const char*)(xl0 + (size_t)t * CCH + c8 * 8));
            } else {
                asm volatile("st.shared.v4.b32 [%0], {%1, %1, %1, %1};" :: "r"(ab_h + sw), "r"(0u) : "memory");
                asm volatile("st.shared.v4.b32 [%0], {%1, %1, %1, %1};" :: "r"(ab_l + sw), "r"(0u) : "memory");
            }
        }
    };

    // warp layout: 2 (M) x 4 (N); warp tile 32 x 32
    const int wm = wid & 1, wn = wid >> 1;
    const int lr = lane & 7, g = lane >> 3;
    const int rA0 = wm * 32 + lr + ((g & 1) << 3);
    const int kA  = ((g >> 1) & 1) << 4;
    const int rB0 = wn * 32 + lr + (((g >> 1) & 1) << 3);
    const int kB  = (g & 1) << 4;

    float acc[2][4][4];
#pragma unroll
    for (int mt = 0; mt < 2; mt++)
#pragma unroll
        for (int j = 0; j < 4; j++)
#pragma unroll
            for (int q = 0; q < 4; q++) acc[mt][j][q] = 0.f;

    load_stage(0, 0);
    cpcommit();
    for (int s = 0; s < S; s++) {
        int buf = s & 1;
        if (s + 1 < S) { load_stage(s + 1, buf ^ 1); cpcommit(); cpwait<1>(); }
        else cpwait<0>();
        __syncthreads();

        const uint32_t ab_h = sb + buf * 16384;
        const uint32_t ab_l = ab_h + 8192;
        const uint32_t bb_h = sb + OFF_B + buf * 32768;
        const uint32_t bb_l = bb_h + 16384;
#pragma unroll
        for (int kk = 0; kk < 4; kk++) {
            uint32_t Ah[2][4], Al[2][4];
#pragma unroll
            for (int mt = 0; mt < 2; mt++) {
                int row = rA0 + mt * 16;
                uint32_t off = row * 128 + (uint32_t)((kk * 32 + kA) ^ ((row & 7) << 4));
                ldsm4(Ah[mt], ab_h + off);
                ldsm4(Al[mt], ab_l + off);
            }
#pragma unroll
            for (int ng = 0; ng < 2; ng++) {
                int row = rB0 + ng * 16;
                uint32_t off = row * 128 + (uint32_t)((kk * 32 + kB) ^ ((row & 7) << 4));
                uint32_t Bh[4], Bl[4];
                ldsm4(Bh, bb_h + off);
                ldsm4(Bl, bb_l + off);
                // 12 MMAs as 4 independent chains
                mma16816(acc[0][2 * ng],     Ah[0], Bh[0], Bh[1]);
                mma16816(acc[0][2 * ng + 1], Ah[0], Bh[2], Bh[3]);
                mma16816(acc[1][2 * ng],     Ah[1], Bh[0], Bh[1]);
                mma16816(acc[1][2 * ng + 1], Ah[1], Bh[2], Bh[3]);
                mma16816(acc[0][2 * ng],     Al[0], Bh[0], Bh[1]);
                mma16816(acc[0][2 * ng + 1], Al[0], Bh[2], Bh[3]);
                mma16816(acc[1][2 * ng],     Al[1], Bh[0], Bh[1]);
                mma16816(acc[1][2 * ng + 1], Al[1], Bh[2], Bh[3]);
                mma16816(acc[0][2 * ng],     Ah[0], Bl[0], Bl[1]);
                mma16816(acc[0][2 * ng + 1], Ah[0], Bl[2], Bl[3]);
                mma16816(acc[1][2 * ng],     Ah[1], Bl[0], Bl[1]);
                mma16816(acc[1][2 * ng + 1], Ah[1], Bl[2], Bl[3]);
            }
        }
        __syncthreads();
    }

    // ---- write raw fp32 GEMM output to scratch ----
#pragma unroll
    for (int mt = 0; mt < 2; mt++) {
        int r0 = t0 + wm * 32 + mt * 16 + (lane >> 2);
#pragma unroll
        for (int j = 0; j < 4; j++) {
            int cg = nh * 128 + wn * 32 + j * 8 + (lane & 3) * 2;
            *(float2*)&g_cv[((size_t)b * T_EN + r0)     * C_H + cg] = make_float2(acc[mt][j][0], acc[mt][j][1]);
            *(float2*)&g_cv[((size_t)b * T_EN + r0 + 8) * C_H + cg] = make_float2(acc[mt][j][2], acc[mt][j][3]);
        }
    }
}

// ---------------- LN over g_cv rows -> h1 split bf16 (conv1 path) ----------------
__global__ void ln1_kernel(const float* __restrict__ bias,
                           const float* __restrict__ gamma, const float* __restrict__ beta) {
    int w = threadIdx.x >> 5, lane = threadIdx.x & 31;
    int row = blockIdx.x * 8 + w;            // 16384 rows, grid 2048
    const float* src = g_cv + (size_t)row * C_H;
    float v[8], sum = 0.f, sq = 0.f;
#pragma unroll
    for (int i = 0; i < 2; i++) {
        float4 x4 = ((const float4*)src)[lane * 2 + i];
        int c = lane * 8 + i * 4;
        v[i*4+0] = fmaxf(x4.x + bias[c],     0.f);
        v[i*4+1] = fmaxf(x4.y + bias[c + 1], 0.f);
        v[i*4+2] = fmaxf(x4.z + bias[c + 2], 0.f);
        v[i*4+3] = fmaxf(x4.w + bias[c + 3], 0.f);
    }
#pragma unroll
    for (int k = 0; k < 8; k++) { sum += v[k]; sq += v[k] * v[k]; }
#pragma unroll
    for (int o = 16; o; o >>= 1) {
        sum += __shfl_xor_sync(0xffffffffu, sum, o);
        sq  += __shfl_xor_sync(0xffffffffu, sq,  o);
    }
    float m  = sum * (1.f / 256.f);
    float rv = rsqrtf(sq * (1.f / 256.f) - m * m + 1e-5f);
    __nv_bfloat16 hb[8], lb_[8];
#pragma unroll
    for (int k = 0; k < 8; k++) {
        int c = lane * 8 + k;
        float n = (v[k] - m) * rv * gamma[c] + beta[c];
        split_bf16(n, hb[k], lb_[k]);
    }
    *(uint4*)(g_h1h + (size_t)row * C_H + lane * 8) = *(uint4*)hb;
    *(uint4*)(g_h1l + (size_t)row * C_H + lane * 8) = *(uint4*)lb_;
}

// ---------------- LN + linear over g_cv rows -> out2 (conv2 path) ----------------
__global__ void ln2_kernel(const float* __restrict__ bias,
                           const float* __restrict__ gamma, const float* __restrict__ beta,
                           const float* __restrict__ lw, const float* __restrict__ lbp,
                           float* __restrict__ out2) {
    int w = threadIdx.x >> 5, lane = threadIdx.x & 31;
    int row = blockIdx.x * 8 + w;
    const float* src = g_cv + (size_t)row * C_H;
    float v[8], sum = 0.f, sq = 0.f;
#pragma unroll
    for (int i = 0; i < 2; i++) {
        float4 x4 = ((const float4*)src)[lane * 2 + i];
        int c = lane * 8 + i * 4;
        v[i*4+0] = fmaxf(x4.x + bias[c],     0.f);
        v[i*4+1] = fmaxf(x4.y + bias[c + 1], 0.f);
        v[i*4+2] = fmaxf(x4.z + bias[c + 2], 0.f);
        v[i*4+3] = fmaxf(x4.w + bias[c + 3], 0.f);
    }
#pragma unroll
    for (int k = 0; k < 8; k++) { sum += v[k]; sq += v[k] * v[k]; }
#pragma unroll
    for (int o = 16; o; o >>= 1) {
        sum += __shfl_xor_sync(0xffffffffu, sum, o);
        sq  += __shfl_xor_sync(0xffffffffu, sq,  o);
    }
    float m  = sum * (1.f / 256.f);
    float rv = rsqrtf(sq * (1.f / 256.f) - m * m + 1e-5f);
    float dot = 0.f;
#pragma unroll
    for (int k = 0; k < 8; k++) {
        int c = lane * 8 + k;
        float n = (v[k] - m) * rv * gamma[c] + beta[c];
        dot += n * lw[c];
    }
#pragma unroll
    for (int o = 16; o; o >>= 1) dot += __shfl_xor_sync(0xffffffffu, dot, o);
    if (lane == 0) {
        int b = row >> 10, t = row & (T_EN - 1);
        out2[row] = (t < g_srclen[b]) ? (dot + lbp[0]) : 0.f;
    }
}

// ---------------- scatter ones into attn^T ----------------
__global__ void ones_kernel(float* __restrict__ out4, int tde) {
    int i = blockIdx.x * blockDim.x + threadIdx.x;
    if (i >= BB * tde) return;
    int b = i / tde, ty = i % tde;
    int tx = g_txmap[b * T_DE_MAX + ty];
    if (tx >= 0) out4[((size_t)b * tde + ty) * T_EN + tx] = 1.0f;
}

// ---------------- encoder_output gather: out3[b][c][ty] = enc[b][tx(ty)][c] ----------------
__global__ void gather3_kernel(const float* __restrict__ enc, float* __restrict__ out3, int tde) {
    int b = blockIdx.y;
    int ty = blockIdx.x * 256 + threadIdx.x;
    if (ty >= tde) return;
    int tx = g_txmap[b * T_DE_MAX + ty];
    float* ob = out3 + (size_t)b * C_IN * tde + ty;
    if (tx < 0) {
        for (int c = 0; c < C_IN; c++) ob[(size_t)c * tde] = 0.f;
    } else {
        const float4* e4 = (const float4*)(enc + ((size_t)b * T_EN + tx) * C_IN);
        for (int c4 = 0; c4 < C_IN / 4; c4++) {
            float4 v = e4[c4];
            ob[(size_t)(4 * c4 + 0) * tde] = v.x;
            ob[(size_t)(4 * c4 + 1) * tde] = v.y;
            ob[(size_t)(4 * c4 + 2) * tde] = v.z;
            ob[(size_t)(4 * c4 + 3) * tde] = v.w;
        }
    }
}

// ---------------- launcher ----------------
extern "C" void kernel_launch(void* const* d_in, const int* in_sizes, int n_in,
                              void* d_out, int out_size) {
    const float* enc    = (const float*)d_in[0];
    const float* encres = (const float*)d_in[1];
    const float* dur    = (const float*)d_in[2];
    const float* c1w    = (const float*)d_in[3];
    const float* c1b    = (const float*)d_in[4];
    const float* g1     = (const float*)d_in[5];
    const float* b1     = (const float*)d_in[6];
    const float* c2w    = (const float*)d_in[7];
    const float* c2b    = (const float*)d_in[8];
    const float* g2     = (const float*)d_in[9];
    const float* b2     = (const float*)d_in[10];
    const float* lw     = (const float*)d_in[11];
    const float* lb     = (const float*)d_in[12];

    float* out = (float*)d_out;
    int tde = (int)(((long long)out_size - (long long)BB * T_EN) /
                    (2LL * BB * T_EN + (long long)BB * C_IN));
    if (tde <= 0 || tde > T_DE_MAX) return;

    float* out1 = out;                                    // [B, T_EN, T_DE] zeros
    float* out2 = out1 + (size_t)BB * T_EN * tde;         // [B, T_EN]
    float* out3 = out2 + (size_t)BB * T_EN;               // [B, C_IN, T_DE]
    float* out4 = out3 + (size_t)BB * C_IN * tde;         // [B, T_DE, T_EN]

    cudaFuncSetAttribute(mma_conv<C_IN, false>, cudaFuncAttributeMaxDynamicSharedMemorySize, CONV_SMEM);
    cudaFuncSetAttribute(mma_conv<C_H,  true >, cudaFuncAttributeMaxDynamicSharedMemorySize, CONV_SMEM);

    cudaMemsetAsync(out1, 0, (size_t)BB * T_EN * tde * sizeof(float));
    cudaMemsetAsync(out4, 0, (size_t)BB * T_EN * tde * sizeof(float));

    prep_kernel<<<1024, 256>>>(c1w, c2w, encres);
    scan_kernel<<<BB, T_EN>>>(dur, tde);

    mma_conv<C_IN, false><<<dim3(T_EN / 64, BB, 2), 256, CONV_SMEM>>>();
    ln1_kernel<<<BB * T_EN / 8, 256>>>(c1b, g1, b1);
    mma_conv<C_H,  true ><<<dim3(T_EN / 64, BB, 2), 256, CONV_SMEM>>>();
    ln2_kernel<<<BB * T_EN / 8, 256>>>(c2b, g2, b2, lw, lb, out2);

    ones_kernel<<<(BB * tde + 255) / 256, 256>>>(out4, tde);
    gather3_kernel<<<dim3((tde + 255) / 256, BB), 256>>>(enc, out3, tde);
}